// round 4
// baseline (speedup 1.0000x reference)
#include <cuda_runtime.h>
#include <cuda_bf16.h>

// Problem constants (B=1, C=2, T=64, V=2, NX=512, NY=512, DX=0.1)
#define T_DIM      64
#define NY_DIM     512
#define NXY        (512 * 512)               // elements per (t, v) plane
#define CH_PER_T   (NXY / 4)                 // 65536 float4 chunks per plane per t
#define BLKS_PER_T 8
#define NTHREADS   256
#define CH_PER_BLK (CH_PER_T / BLKS_PER_T)   // 8192
#define OUTER      8                          // 8 outer * 4 inner = 32 chunks/thread

// Scratch: g_partial fully overwritten each launch; g_count reset to 0 by the
// last-arriving block of each t -> graph-replay safe.
__device__ float        g_partial[T_DIM * BLKS_PER_T];
__device__ unsigned int g_count[T_DIM];   // zero-initialized at load

__global__ __launch_bounds__(NTHREADS)
void fused_kernel(const float* __restrict__ x,
                  const float* __restrict__ idrv,
                  const float* __restrict__ w1,
                  const float* __restrict__ b1,
                  const float* __restrict__ w2,
                  const float* __restrict__ b2,
                  float* __restrict__ out) {
    const int t    = blockIdx.x / BLKS_PER_T;
    const int blk  = blockIdx.x % BLKS_PER_T;
    const int lane = threadIdx.x & 31;

    // x layout: [b][c][t][v][ix][iy]; c=0 only.
    const float*  nptr = x + (size_t)t * (2u * NXY);
    const float*  pptr = nptr + NXY;
    const float4* n4   = reinterpret_cast<const float4*>(nptr);
    const float4* p4   = reinterpret_cast<const float4*>(pptr);

    const float inv2 = 0.5f / 0.1f;   // 5.0  (central)
    const float inv1 = 1.0f / 0.1f;   // 10.0 (one-sided)

    float acc = 0.0f;
    const int base0 = blk * CH_PER_BLK + threadIdx.x;

    for (int o = 0; o < OUTER; ++o) {
#pragma unroll
        for (int j = 0; j < 4; ++j) {
            const int c = base0 + (o * 4 + j) * NTHREADS;   // float4 chunk idx
            const float4 nv = __ldg(n4 + c);
            const float4 pv = __ldg(p4 + c);

            const int r = c & (NY_DIM / 4 - 1);   // chunk within row (0..127)
            // Halo via warp shuffle: lane == c mod 32, neighbor chunks are
            // adjacent lanes. Only warp-edge lanes fall back to a scalar load
            // (L1 hit: same lines the vector loads fetched).
            float pm1 = __shfl_up_sync(0xffffffffu, pv.w, 1);
            float pp4 = __shfl_down_sync(0xffffffffu, pv.x, 1);
            if (lane == 0  && r != 0)   pm1 = __ldg(pptr + 4 * (size_t)c - 1);
            if (lane == 31 && r != 127) pp4 = __ldg(pptr + 4 * (size_t)c + 4);

            const float g0 = (r == 0)   ? (pv.y - pv.x) * inv1 : (pv.y - pm1)  * inv2;
            const float g1 =                                     (pv.z - pv.x) * inv2;
            const float g2 =                                     (pv.w - pv.y) * inv2;
            const float g3 = (r == 127) ? (pv.w - pv.z) * inv1 : (pp4  - pv.z) * inv2;

            acc += nv.x * g0 + nv.y * g1 + nv.z * g2 + nv.w * g3;
        }
    }

    // ---- Deterministic block reduction to thread 0 ----
    __shared__ float sm[NTHREADS / 32];
#pragma unroll
    for (int o = 16; o > 0; o >>= 1)
        acc += __shfl_down_sync(0xffffffffu, acc, o);
    if (lane == 0) sm[threadIdx.x >> 5] = acc;
    __syncthreads();

    __shared__ bool is_last;
    if (threadIdx.x == 0) {
        float total = 0.0f;
#pragma unroll
        for (int w = 0; w < NTHREADS / 32; ++w) total += sm[w];
        g_partial[blockIdx.x] = total;
        __threadfence();
        unsigned v = atomicAdd(&g_count[t], 1u);
        is_last = (v == BLKS_PER_T - 1);
        if (is_last) g_count[t] = 0;     // reset for next graph replay
    }
    __syncthreads();

    // ---- Last block of this t: sum 8 partials + tiny MLP (warp 0) ----
    if (is_last && threadIdx.x < 32) {
        __threadfence();                 // acquire: partials visible
        float v = (lane < BLKS_PER_T) ? g_partial[t * BLKS_PER_T + lane] : 0.0f;
#pragma unroll
        for (int o2 = 4; o2 > 0; o2 >>= 1)
            v += __shfl_down_sync(0xffffffffu, v, o2);
        if (lane == 0) {
            const float gamma = -v * (1.0f / (float)NXY);
            const float f0 = idrv[t];
            const float f1 = gamma;
            float o = b2[0];
#pragma unroll
            for (int h = 0; h < 4; ++h) {
                const float pre = w1[2 * h] * f0 + w1[2 * h + 1] * f1 + b1[h];
                // JAX default gelu (approximate=True, tanh form)
                const float g = 0.5f * pre *
                    (1.0f + tanhf(0.7978845608028654f *
                                  (pre + 0.044715f * pre * pre * pre)));
                o += w2[h] * g;
            }
            out[t] = o;
        }
    }
}

extern "C" void kernel_launch(void* const* d_in, const int* in_sizes, int n_in,
                              void* d_out, int out_size) {
    const float* x    = (const float*)d_in[0];  // (1,2,64,2,512,512) f32
    const float* idrv = (const float*)d_in[1];  // (1,64)  f32
    const float* w1   = (const float*)d_in[2];  // (4,2)   f32
    const float* b1   = (const float*)d_in[3];  // (4,)    f32
    const float* w2   = (const float*)d_in[4];  // (1,4)   f32
    const float* b2   = (const float*)d_in[5];  // (1,)    f32
    float* out        = (float*)d_out;          // 64 f32

    fused_kernel<<<T_DIM * BLKS_PER_T, NTHREADS>>>(x, idrv, w1, b1, w2, b2, out);
}

// round 6
// speedup vs baseline: 1.2094x; 1.2094x over previous
#include <cuda_runtime.h>
#include <cuda_bf16.h>

// Problem constants (B=1, C=2, T=64, V=2, NX=512, NY=512, DX=0.1)
#define T_DIM      64
#define NY_DIM     512
#define NXY        (512 * 512)               // elements per (t, v) plane
#define CH_PER_T   (NXY / 4)                 // 65536 float4 chunks per plane per t
#define BLKS_PER_T 16                        // 1024 blocks total: ~0.86 of one full wave
#define NTHREADS   256
#define CH_PER_BLK (CH_PER_T / BLKS_PER_T)   // 4096
#define OUTER      4                          // 4 outer * 4 inner = 16 chunks/thread

// Scratch: g_partial fully overwritten each launch; g_count reset to 0 by the
// last-arriving block of each t -> graph-replay safe.
__device__ float        g_partial[T_DIM * BLKS_PER_T];
__device__ unsigned int g_count[T_DIM];   // zero-initialized at load

__global__ __launch_bounds__(NTHREADS)
void fused_kernel(const float* __restrict__ x,
                  const float* __restrict__ idrv,
                  const float* __restrict__ w1,
                  const float* __restrict__ b1,
                  const float* __restrict__ w2,
                  const float* __restrict__ b2,
                  float* __restrict__ out) {
    const int t    = blockIdx.x / BLKS_PER_T;
    const int blk  = blockIdx.x % BLKS_PER_T;
    const int lane = threadIdx.x & 31;

    // x layout: [b][c][t][v][ix][iy]; c=0 only.
    const float*  nptr = x + (size_t)t * (2u * NXY);
    const float*  pptr = nptr + NXY;
    const float4* n4   = reinterpret_cast<const float4*>(nptr);
    const float4* p4   = reinterpret_cast<const float4*>(pptr);

    const float inv2 = 0.5f / 0.1f;   // 5.0  (central)
    const float inv1 = 1.0f / 0.1f;   // 10.0 (one-sided)

    float acc = 0.0f;
    const int base0 = blk * CH_PER_BLK + threadIdx.x;

    for (int o = 0; o < OUTER; ++o) {
#pragma unroll
        for (int j = 0; j < 4; ++j) {
            const int c = base0 + (o * 4 + j) * NTHREADS;   // float4 chunk idx
            const float4 nv = __ldg(n4 + c);
            const float4 pv = __ldg(p4 + c);

            const int r = c & (NY_DIM / 4 - 1);   // chunk within row (0..127)
            // Halo via warp shuffle: lane == c mod 32, neighbor chunks are
            // adjacent lanes. Only warp-edge lanes fall back to a scalar load
            // (L1/L2 hit: same lines the vector loads fetched).
            float pm1 = __shfl_up_sync(0xffffffffu, pv.w, 1);
            float pp4 = __shfl_down_sync(0xffffffffu, pv.x, 1);
            if (lane == 0  && r != 0)   pm1 = __ldg(pptr + 4 * (size_t)c - 1);
            if (lane == 31 && r != 127) pp4 = __ldg(pptr + 4 * (size_t)c + 4);

            const float g0 = (r == 0)   ? (pv.y - pv.x) * inv1 : (pv.y - pm1)  * inv2;
            const float g1 =                                     (pv.z - pv.x) * inv2;
            const float g2 =                                     (pv.w - pv.y) * inv2;
            const float g3 = (r == 127) ? (pv.w - pv.z) * inv1 : (pp4  - pv.z) * inv2;

            acc += nv.x * g0 + nv.y * g1 + nv.z * g2 + nv.w * g3;
        }
    }

    // ---- Deterministic block reduction to thread 0 ----
    __shared__ float sm[NTHREADS / 32];
#pragma unroll
    for (int o = 16; o > 0; o >>= 1)
        acc += __shfl_down_sync(0xffffffffu, acc, o);
    if (lane == 0) sm[threadIdx.x >> 5] = acc;
    __syncthreads();

    __shared__ bool is_last;
    if (threadIdx.x == 0) {
        float total = 0.0f;
#pragma unroll
        for (int w = 0; w < NTHREADS / 32; ++w) total += sm[w];
        g_partial[blockIdx.x] = total;
        __threadfence();
        unsigned v = atomicAdd(&g_count[t], 1u);
        is_last = (v == BLKS_PER_T - 1);
        if (is_last) g_count[t] = 0;     // reset for next graph replay
    }
    __syncthreads();

    // ---- Last block of this t: sum 16 partials + tiny MLP (warp 0) ----
    if (is_last && threadIdx.x < 32) {
        __threadfence();                 // acquire: partials visible
        float v = (lane < BLKS_PER_T) ? g_partial[t * BLKS_PER_T + lane] : 0.0f;
#pragma unroll
        for (int o2 = 8; o2 > 0; o2 >>= 1)
            v += __shfl_down_sync(0xffffffffu, v, o2);
        if (lane == 0) {
            const float gamma = -v * (1.0f / (float)NXY);
            const float f0 = idrv[t];
            const float f1 = gamma;
            float o = b2[0];
#pragma unroll
            for (int h = 0; h < 4; ++h) {
                const float pre = w1[2 * h] * f0 + w1[2 * h + 1] * f1 + b1[h];
                // JAX default gelu (approximate=True, tanh form)
                const float g = 0.5f * pre *
                    (1.0f + tanhf(0.7978845608028654f *
                                  (pre + 0.044715f * pre * pre * pre)));
                o += w2[h] * g;
            }
            out[t] = o;
        }
    }
}

extern "C" void kernel_launch(void* const* d_in, const int* in_sizes, int n_in,
                              void* d_out, int out_size) {
    const float* x    = (const float*)d_in[0];  // (1,2,64,2,512,512) f32
    const float* idrv = (const float*)d_in[1];  // (1,64)  f32
    const float* w1   = (const float*)d_in[2];  // (4,2)   f32
    const float* b1   = (const float*)d_in[3];  // (4,)    f32
    const float* w2   = (const float*)d_in[4];  // (1,4)   f32
    const float* b2   = (const float*)d_in[5];  // (1,)    f32
    float* out        = (float*)d_out;          // 64 f32

    fused_kernel<<<T_DIM * BLKS_PER_T, NTHREADS>>>(x, idrv, w1, b1, w2, b2, out);
}

// round 7
// speedup vs baseline: 1.2901x; 1.0667x over previous
#include <cuda_runtime.h>
#include <cuda_bf16.h>

// Problem constants (B=1, C=2, T=64, V=2, NX=512, NY=512, DX=0.1)
#define T_DIM      64
#define NY_DIM     512
#define NXY        (512 * 512)               // elements per (t, v) plane
#define CH_PER_T   (NXY / 4)                 // 65536 float4 chunks per plane per t
#define BLKS_PER_T 8                         // 512 blocks total
#define NTHREADS   256
#define CH_PER_BLK (CH_PER_T / BLKS_PER_T)   // 8192
#define OUTER      8                          // 8 outer * 4 batched chunks = 32/thread

// Scratch: g_partial fully overwritten each launch; g_count reset to 0 by the
// last-arriving block of each t -> graph-replay safe.
__device__ float        g_partial[T_DIM * BLKS_PER_T];
__device__ unsigned int g_count[T_DIM];   // zero-initialized at load

__global__ __launch_bounds__(NTHREADS, 4)   // allow up to 64 regs: front-batch 8 LDG.128
void fused_kernel(const float* __restrict__ x,
                  const float* __restrict__ idrv,
                  const float* __restrict__ w1,
                  const float* __restrict__ b1,
                  const float* __restrict__ w2,
                  const float* __restrict__ b2,
                  float* __restrict__ out) {
    const int t    = blockIdx.x / BLKS_PER_T;
    const int blk  = blockIdx.x % BLKS_PER_T;
    const int lane = threadIdx.x & 31;

    // x layout: [b][c][t][v][ix][iy]; c=0 only.
    const float*  nptr = x + (size_t)t * (2u * NXY);
    const float*  pptr = nptr + NXY;
    const float4* n4   = reinterpret_cast<const float4*>(nptr);
    const float4* p4   = reinterpret_cast<const float4*>(pptr);

    const float inv2 = 0.5f / 0.1f;   // 5.0  (central)
    const float inv1 = 1.0f / 0.1f;   // 10.0 (one-sided)

    float acc = 0.0f;
    const int base0 = blk * CH_PER_BLK + threadIdx.x;

    for (int o = 0; o < OUTER; ++o) {
        const int cb = base0 + o * 4 * NTHREADS;

        // ---- Front-batched independent loads: 8 LDG.128 in flight ----
        float4 nv[4], pv[4];
#pragma unroll
        for (int j = 0; j < 4; ++j) pv[j] = __ldg(p4 + (cb + j * NTHREADS));
#pragma unroll
        for (int j = 0; j < 4; ++j) nv[j] = __ldg(n4 + (cb + j * NTHREADS));

        // ---- Compute ----
#pragma unroll
        for (int j = 0; j < 4; ++j) {
            const int c = cb + j * NTHREADS;
            const int r = c & (NY_DIM / 4 - 1);   // chunk within row (0..127)
            // Halo via warp shuffle: lane == c mod 32, neighbor chunks are
            // adjacent lanes. Warp-edge lanes fall back to a scalar load
            // (L1/L2 hit: same lines the vector loads fetched).
            float pm1 = __shfl_up_sync(0xffffffffu, pv[j].w, 1);
            float pp4 = __shfl_down_sync(0xffffffffu, pv[j].x, 1);
            if (lane == 0  && r != 0)   pm1 = __ldg(pptr + 4 * (size_t)c - 1);
            if (lane == 31 && r != 127) pp4 = __ldg(pptr + 4 * (size_t)c + 4);

            const float g0 = (r == 0)   ? (pv[j].y - pv[j].x) * inv1 : (pv[j].y - pm1)     * inv2;
            const float g1 =                                           (pv[j].z - pv[j].x) * inv2;
            const float g2 =                                           (pv[j].w - pv[j].y) * inv2;
            const float g3 = (r == 127) ? (pv[j].w - pv[j].z) * inv1 : (pp4     - pv[j].z) * inv2;

            acc += nv[j].x * g0 + nv[j].y * g1 + nv[j].z * g2 + nv[j].w * g3;
        }
    }

    // ---- Deterministic block reduction to thread 0 ----
    __shared__ float sm[NTHREADS / 32];
#pragma unroll
    for (int o = 16; o > 0; o >>= 1)
        acc += __shfl_down_sync(0xffffffffu, acc, o);
    if (lane == 0) sm[threadIdx.x >> 5] = acc;
    __syncthreads();

    __shared__ bool is_last;
    if (threadIdx.x == 0) {
        float total = 0.0f;
#pragma unroll
        for (int w = 0; w < NTHREADS / 32; ++w) total += sm[w];
        g_partial[blockIdx.x] = total;
        __threadfence();
        unsigned v = atomicAdd(&g_count[t], 1u);
        is_last = (v == BLKS_PER_T - 1);
        if (is_last) g_count[t] = 0;     // reset for next graph replay
    }
    __syncthreads();

    // ---- Last block of this t: sum 8 partials + tiny MLP (warp 0) ----
    if (is_last && threadIdx.x < 32) {
        __threadfence();                 // acquire: partials visible
        float v = (lane < BLKS_PER_T) ? g_partial[t * BLKS_PER_T + lane] : 0.0f;
#pragma unroll
        for (int o2 = 4; o2 > 0; o2 >>= 1)
            v += __shfl_down_sync(0xffffffffu, v, o2);
        if (lane == 0) {
            const float gamma = -v * (1.0f / (float)NXY);
            const float f0 = idrv[t];
            const float f1 = gamma;
            float o = b2[0];
#pragma unroll
            for (int h = 0; h < 4; ++h) {
                const float pre = w1[2 * h] * f0 + w1[2 * h + 1] * f1 + b1[h];
                // JAX default gelu (approximate=True, tanh form)
                const float g = 0.5f * pre *
                    (1.0f + tanhf(0.7978845608028654f *
                                  (pre + 0.044715f * pre * pre * pre)));
                o += w2[h] * g;
            }
            out[t] = o;
        }
    }
}

extern "C" void kernel_launch(void* const* d_in, const int* in_sizes, int n_in,
                              void* d_out, int out_size) {
    const float* x    = (const float*)d_in[0];  // (1,2,64,2,512,512) f32
    const float* idrv = (const float*)d_in[1];  // (1,64)  f32
    const float* w1   = (const float*)d_in[2];  // (4,2)   f32
    const float* b1   = (const float*)d_in[3];  // (4,)    f32
    const float* w2   = (const float*)d_in[4];  // (1,4)   f32
    const float* b2   = (const float*)d_in[5];  // (1,)    f32
    float* out        = (float*)d_out;          // 64 f32

    fused_kernel<<<T_DIM * BLKS_PER_T, NTHREADS>>>(x, idrv, w1, b1, w2, b2, out);
}